// round 1
// baseline (speedup 1.0000x reference)
#include <cuda_runtime.h>

// Problem constants (fixed shapes for this problem instance)
#define NB    8
#define DIM   512          // input feature dim D
#define HW    48
#define LSEQ  2304         // H*W
#define FD    512          // projection output dim F
#define MTOT  (NB * LSEQ)  // 18432 total rows
#define EPSN  1e-5f
#define SCORE_SCALE 0.044194173824159216f  // 1/sqrt(512)

// Scratch (device globals; no runtime allocation allowed)
__device__ float g_Q[MTOT * FD];                 // 37.7 MB
__device__ float g_K[MTOT * FD];
__device__ float g_V[MTOT * FD];
__device__ float g_S[NB * LSEQ * LSEQ];          // 170 MB scores/probs

// ---------------------------------------------------------------------------
// Kernel 1: fused projection GEMM  T = tanh(flat @ W^T + b)   for q,k,v
//   flat[m, d] = x[n, d, l]  (m = n*LSEQ + l)  -> A-tile loads are coalesced
//   over m (x contiguous in l). 128x128x16 tile, 8x8 per thread.
// ---------------------------------------------------------------------------
__global__ __launch_bounds__(256) void proj_kernel(
    const float* __restrict__ x,
    const float* __restrict__ Wq, const float* __restrict__ bq,
    const float* __restrict__ Wk, const float* __restrict__ bk,
    const float* __restrict__ Wv, const float* __restrict__ bv)
{
    __shared__ __align__(16) float As[16][132];
    __shared__ __align__(16) float Bs[16][132];

    const float* W; const float* bias; float* out;
    if (blockIdx.z == 0)      { W = Wq; bias = bq; out = g_Q; }
    else if (blockIdx.z == 1) { W = Wk; bias = bk; out = g_K; }
    else                      { W = Wv; bias = bv; out = g_V; }

    const int m0 = blockIdx.y * 128;     // row block (aligned inside a batch: 128 | 2304)
    const int f0 = blockIdx.x * 128;     // output-feature block
    const int n  = m0 / LSEQ;
    const int l0 = m0 % LSEQ;
    const float* xb = x + (size_t)n * DIM * LSEQ;

    const int tid = threadIdx.x;
    const int tx = tid & 15;
    const int ty = tid >> 4;

    float acc[8][8];
#pragma unroll
    for (int i = 0; i < 8; i++)
#pragma unroll
        for (int j = 0; j < 8; j++) acc[i][j] = 0.0f;

    for (int k0 = 0; k0 < DIM; k0 += 16) {
        // A tile: As[kk][m] = xb[(k0+kk)*LSEQ + l0 + m]  (m-fastest: coalesced)
#pragma unroll
        for (int i = 0; i < 8; i++) {
            int idx = tid + i * 256;
            int m = idx & 127, kk = idx >> 7;
            As[kk][m] = xb[(size_t)(k0 + kk) * LSEQ + (l0 + m)];
        }
        // B tile: Bs[kk][f] = W[(f0+f)*DIM + k0+kk]  (kk-fastest: 64B runs)
#pragma unroll
        for (int i = 0; i < 8; i++) {
            int idx = tid + i * 256;
            int kk = idx & 15, f = idx >> 4;
            Bs[kk][f] = W[(size_t)(f0 + f) * DIM + (k0 + kk)];
        }
        __syncthreads();
#pragma unroll
        for (int kk = 0; kk < 16; kk++) {
            float4 a0 = *(const float4*)&As[kk][ty * 8];
            float4 a1 = *(const float4*)&As[kk][ty * 8 + 4];
            float4 b0 = *(const float4*)&Bs[kk][tx * 8];
            float4 b1 = *(const float4*)&Bs[kk][tx * 8 + 4];
            float a[8] = {a0.x, a0.y, a0.z, a0.w, a1.x, a1.y, a1.z, a1.w};
            float b[8] = {b0.x, b0.y, b0.z, b0.w, b1.x, b1.y, b1.z, b1.w};
#pragma unroll
            for (int i = 0; i < 8; i++)
#pragma unroll
                for (int j = 0; j < 8; j++)
                    acc[i][j] = fmaf(a[i], b[j], acc[i][j]);
        }
        __syncthreads();
    }

#pragma unroll
    for (int i = 0; i < 8; i++) {
        size_t m = (size_t)(m0 + ty * 8 + i);
#pragma unroll
        for (int j = 0; j < 8; j++) {
            int f = f0 + tx * 8 + j;
            out[m * FD + f] = tanhf(acc[i][j] + bias[f]);
        }
    }
}

// ---------------------------------------------------------------------------
// Kernel 2: double instance norm, literal two-pass, in place. One block/row.
// ---------------------------------------------------------------------------
__device__ __forceinline__ float rsum128(float x, volatile float* red, int tid)
{
#pragma unroll
    for (int o = 16; o > 0; o >>= 1) x += __shfl_down_sync(0xffffffffu, x, o);
    if ((tid & 31) == 0) red[tid >> 5] = x;
    __syncthreads();
    float t = (red[0] + red[1]) + (red[2] + red[3]);
    __syncthreads();
    return t;
}

__global__ __launch_bounds__(128) void inorm_kernel()
{
    float* buf = (blockIdx.y == 0) ? g_Q : (blockIdx.y == 1) ? g_K : g_V;
    float4* row = (float4*)(buf + (size_t)blockIdx.x * FD);
    __shared__ float red[4];
    const int tid = threadIdx.x;
    float4 v = row[tid];

    // pass 1
    float s  = rsum128(v.x + v.y + v.z + v.w, red, tid);
    float mu = s * (1.0f / FD);
    v.x -= mu; v.y -= mu; v.z -= mu; v.w -= mu;
    float sq = rsum128(v.x * v.x + v.y * v.y + v.z * v.z + v.w * v.w, red, tid);
    float r1 = rsqrtf(sq * (1.0f / FD) + EPSN);
    v.x *= r1; v.y *= r1; v.z *= r1; v.w *= r1;

    // pass 2 (literal, matches reference's nested InstanceNorm)
    float s2  = rsum128(v.x + v.y + v.z + v.w, red, tid);
    float mu2 = s2 * (1.0f / FD);
    v.x -= mu2; v.y -= mu2; v.z -= mu2; v.w -= mu2;
    float sq2 = rsum128(v.x * v.x + v.y * v.y + v.z * v.z + v.w * v.w, red, tid);
    float r2  = rsqrtf(sq2 * (1.0f / FD) + EPSN);
    v.x *= r2; v.y *= r2; v.z *= r2; v.w *= r2;

    row[tid] = v;
}

// ---------------------------------------------------------------------------
// Kernel 3: scores S = (Q K^T) * scale   (NT GEMM per batch)
// ---------------------------------------------------------------------------
__global__ __launch_bounds__(256) void scores_kernel()
{
    __shared__ __align__(16) float As[16][132];
    __shared__ __align__(16) float Bs[16][132];
    const int n  = blockIdx.z;
    const int i0 = blockIdx.y * 128;
    const int j0 = blockIdx.x * 128;
    const float* Qb = g_Q + (size_t)n * LSEQ * FD;
    const float* Kb = g_K + (size_t)n * LSEQ * FD;
    float* Sb = g_S + (size_t)n * LSEQ * LSEQ;

    const int tid = threadIdx.x;
    const int tx = tid & 15;
    const int ty = tid >> 4;

    float acc[8][8];
#pragma unroll
    for (int i = 0; i < 8; i++)
#pragma unroll
        for (int j = 0; j < 8; j++) acc[i][j] = 0.0f;

    for (int k0 = 0; k0 < FD; k0 += 16) {
#pragma unroll
        for (int i = 0; i < 8; i++) {
            int idx = tid + i * 256;
            int kk = idx & 15, m = idx >> 4;
            As[kk][m] = Qb[(size_t)(i0 + m) * FD + (k0 + kk)];
            Bs[kk][m] = Kb[(size_t)(j0 + m) * FD + (k0 + kk)];
        }
        __syncthreads();
#pragma unroll
        for (int kk = 0; kk < 16; kk++) {
            float4 a0 = *(const float4*)&As[kk][ty * 8];
            float4 a1 = *(const float4*)&As[kk][ty * 8 + 4];
            float4 b0 = *(const float4*)&Bs[kk][tx * 8];
            float4 b1 = *(const float4*)&Bs[kk][tx * 8 + 4];
            float a[8] = {a0.x, a0.y, a0.z, a0.w, a1.x, a1.y, a1.z, a1.w};
            float b[8] = {b0.x, b0.y, b0.z, b0.w, b1.x, b1.y, b1.z, b1.w};
#pragma unroll
            for (int i = 0; i < 8; i++)
#pragma unroll
                for (int j = 0; j < 8; j++)
                    acc[i][j] = fmaf(a[i], b[j], acc[i][j]);
        }
        __syncthreads();
    }

#pragma unroll
    for (int i = 0; i < 8; i++) {
        size_t r = (size_t)(i0 + ty * 8 + i);
#pragma unroll
        for (int j = 0; j < 8; j++)
            Sb[r * LSEQ + (j0 + tx * 8 + j)] = acc[i][j] * SCORE_SCALE;
    }
}

// ---------------------------------------------------------------------------
// Kernel 4: row softmax over LSEQ=2304 (256 threads x 9 elems, registers)
// ---------------------------------------------------------------------------
__global__ __launch_bounds__(256) void softmax_kernel()
{
    float* row = g_S + (size_t)blockIdx.x * LSEQ;
    __shared__ float red[8];
    const int tid = threadIdx.x;

    float v[9];
    float mx = -1e30f;
#pragma unroll
    for (int i = 0; i < 9; i++) {
        v[i] = row[tid + i * 256];
        mx = fmaxf(mx, v[i]);
    }
#pragma unroll
    for (int o = 16; o > 0; o >>= 1) mx = fmaxf(mx, __shfl_xor_sync(0xffffffffu, mx, o));
    if ((tid & 31) == 0) red[tid >> 5] = mx;
    __syncthreads();
    mx = red[0];
#pragma unroll
    for (int w = 1; w < 8; w++) mx = fmaxf(mx, red[w]);
    __syncthreads();

    float s = 0.0f;
#pragma unroll
    for (int i = 0; i < 9; i++) { v[i] = expf(v[i] - mx); s += v[i]; }
#pragma unroll
    for (int o = 16; o > 0; o >>= 1) s += __shfl_xor_sync(0xffffffffu, s, o);
    if ((tid & 31) == 0) red[tid >> 5] = s;
    __syncthreads();
    s = ((red[0] + red[1]) + (red[2] + red[3])) + ((red[4] + red[5]) + (red[6] + red[7]));
    float inv = 1.0f / s;
#pragma unroll
    for (int i = 0; i < 9; i++) row[tid + i * 256] = v[i] * inv;
}

// ---------------------------------------------------------------------------
// Kernel 5: A = P @ V   (NN GEMM per batch), writes straight into d_out
//   (the reference's final reshape is a raw reinterpret of (N, L, F))
// ---------------------------------------------------------------------------
__global__ __launch_bounds__(256) void pv_kernel(float* __restrict__ out)
{
    __shared__ __align__(16) float As[16][132];
    __shared__ __align__(16) float Bs[16][132];
    const int n  = blockIdx.z;
    const int i0 = blockIdx.y * 128;
    const int f0 = blockIdx.x * 128;
    const float* Pb = g_S + (size_t)n * LSEQ * LSEQ;
    const float* Vb = g_V + (size_t)n * LSEQ * FD;

    const int tid = threadIdx.x;
    const int tx = tid & 15;
    const int ty = tid >> 4;

    float acc[8][8];
#pragma unroll
    for (int i = 0; i < 8; i++)
#pragma unroll
        for (int j = 0; j < 8; j++) acc[i][j] = 0.0f;

    for (int k0 = 0; k0 < LSEQ; k0 += 16) {
#pragma unroll
        for (int i = 0; i < 8; i++) {
            int idx = tid + i * 256;
            { int kk = idx & 15, m = idx >> 4;
              As[kk][m] = Pb[(size_t)(i0 + m) * LSEQ + (k0 + kk)]; }
            { int f = idx & 127, kk = idx >> 7;
              Bs[kk][f] = Vb[(size_t)(k0 + kk) * FD + (f0 + f)]; }
        }
        __syncthreads();
#pragma unroll
        for (int kk = 0; kk < 16; kk++) {
            float4 a0 = *(const float4*)&As[kk][ty * 8];
            float4 a1 = *(const float4*)&As[kk][ty * 8 + 4];
            float4 b0 = *(const float4*)&Bs[kk][tx * 8];
            float4 b1 = *(const float4*)&Bs[kk][tx * 8 + 4];
            float a[8] = {a0.x, a0.y, a0.z, a0.w, a1.x, a1.y, a1.z, a1.w};
            float b[8] = {b0.x, b0.y, b0.z, b0.w, b1.x, b1.y, b1.z, b1.w};
#pragma unroll
            for (int i = 0; i < 8; i++)
#pragma unroll
                for (int j = 0; j < 8; j++)
                    acc[i][j] = fmaf(a[i], b[j], acc[i][j]);
        }
        __syncthreads();
    }

    float* Ob = out + (size_t)n * LSEQ * FD;
#pragma unroll
    for (int i = 0; i < 8; i++) {
        size_t r = (size_t)(i0 + ty * 8 + i);
#pragma unroll
        for (int j = 0; j < 8; j++)
            Ob[r * FD + (f0 + tx * 8 + j)] = acc[i][j];
    }
}

// ---------------------------------------------------------------------------
extern "C" void kernel_launch(void* const* d_in, const int* in_sizes, int n_in,
                              void* d_out, int out_size)
{
    const float* x  = (const float*)d_in[0];
    const float* Wq = (const float*)d_in[1];
    const float* bq = (const float*)d_in[2];
    const float* Wk = (const float*)d_in[3];
    const float* bk = (const float*)d_in[4];
    const float* Wv = (const float*)d_in[5];
    const float* bv = (const float*)d_in[6];
    float* out = (float*)d_out;

    proj_kernel<<<dim3(FD / 128, MTOT / 128, 3), 256>>>(x, Wq, bq, Wk, bk, Wv, bv);
    inorm_kernel<<<dim3(MTOT, 3), 128>>>();
    scores_kernel<<<dim3(LSEQ / 128, LSEQ / 128, NB), 256>>>();
    softmax_kernel<<<NB * LSEQ, 256>>>();
    pv_kernel<<<dim3(FD / 128, LSEQ / 128, NB), 256>>>(out);
}

// round 3
// speedup vs baseline: 2.7149x; 2.7149x over previous
#include <cuda_runtime.h>
#include <cuda_bf16.h>
#include <cstdint>

#define NB    8
#define DIM   512
#define LSEQ  2304
#define FD    512
#define MTOT  (NB * LSEQ)         // 18432
#define MF    ((size_t)MTOT * FD) // 9437184
#define EPSN  1e-5f
#define SCORE_SCALE 0.044194173824159216f   // 1/sqrt(512)

typedef __nv_bfloat16 bf16;

// ---------------- scratch (device globals) ----------------
__device__ bf16  g_flat_h[MF], g_flat_l[MF];         // x^T hi/lo
__device__ bf16  g_Wh[3][FD * DIM], g_Wl[3][FD * DIM];
__device__ bf16  g_Qh[MF], g_Ql[MF];
__device__ bf16  g_Kh[MF], g_Kl[MF];
__device__ bf16  g_Vh[MF], g_Vl[MF];
__device__ bf16  g_VTh[MF], g_VTl[MF];               // V^T per batch (F, L)
__device__ bf16  g_Ph[(size_t)NB * LSEQ * LSEQ], g_Pl[(size_t)NB * LSEQ * LSEQ];
__device__ float g_S[(size_t)NB * LSEQ * LSEQ];      // scores fp32 (front 28.3M floats double as QKV raw)

// ---------------- PTX helpers (plain sm_80+ target only) ----------------
__device__ __forceinline__ uint32_t smem_u32(const void* p) {
    uint32_t a;
    asm("{ .reg .u64 t; cvta.to.shared.u64 t, %1; cvt.u32.u64 %0, t; }" : "=r"(a) : "l"(p));
    return a;
}
__device__ __forceinline__ void cp16(uint32_t dst, const void* src) {
    asm volatile("cp.async.cg.shared.global [%0], [%1], 16;" :: "r"(dst), "l"(src));
}
#define CP_COMMIT() asm volatile("cp.async.commit_group;" ::: "memory")
#define CP_WAIT(N)  asm volatile("cp.async.wait_group %0;" :: "n"(N) : "memory")

__device__ __forceinline__ void ldsm4(uint32_t* r, uint32_t addr) {
    asm volatile("ldmatrix.sync.aligned.m8n8.x4.shared.b16 {%0,%1,%2,%3}, [%4];"
                 : "=r"(r[0]), "=r"(r[1]), "=r"(r[2]), "=r"(r[3]) : "r"(addr));
}
__device__ __forceinline__ void mma16816(float* c, const uint32_t* a, const uint32_t* b) {
    asm volatile("mma.sync.aligned.m16n8k16.row.col.f32.bf16.bf16.f32 "
                 "{%0,%1,%2,%3}, {%4,%5,%6,%7}, {%8,%9}, {%0,%1,%2,%3};"
                 : "+f"(c[0]), "+f"(c[1]), "+f"(c[2]), "+f"(c[3])
                 : "r"(a[0]), "r"(a[1]), "r"(a[2]), "r"(a[3]), "r"(b[0]), "r"(b[1]));
}

__device__ __forceinline__ void split2(float v, bf16& h, bf16& l) {
    h = __float2bfloat16_rn(v);
    l = __float2bfloat16_rn(v - __bfloat162float(h));
}

// ---------------- SMEM geometry ----------------
// tile: 128 rows x 32 bf16 (64B data + 16B pad => 80B stride) = 10240 B
#define TB      10240
#define STAGEB  (4 * TB)          // Ah | Al | Bh | Bl
#define GEMM_SMEM (2 * STAGEB)    // 81920 B

// ===========================================================================
// 3xBF16 mma.sync GEMM: C[m,n] = sum_k A[m,k]*B[n,k]   (A,B K-major, split)
// EPI: 0 = tanh(acc+bias), 1 = acc*scale, 2 = none
// ===========================================================================
template <int EPI>
__global__ void __launch_bounds__(256, 2) gemm3(
    const bf16* __restrict__ Ah, const bf16* __restrict__ Al,
    const bf16* __restrict__ Bh, const bf16* __restrict__ Bl,
    float* __restrict__ C, const float* __restrict__ bias,
    int K, int lda, int ldb, int ldc,
    long long sA, long long sB, long long sC, float scale)
{
    extern __shared__ char smem[];
    const uint32_t sbase = smem_u32(smem);
    const int tid  = threadIdx.x;
    const int lane = tid & 31, wid = tid >> 5;
    const int wm = wid >> 2, wn = wid & 3;

    const int m0 = blockIdx.y * 128;
    const int f0 = blockIdx.x * 128;
    Ah += (long long)blockIdx.z * sA + (size_t)m0 * lda;
    Al += (long long)blockIdx.z * sA + (size_t)m0 * lda;
    Bh += (long long)blockIdx.z * sB + (size_t)f0 * ldb;
    Bl += (long long)blockIdx.z * sB + (size_t)f0 * ldb;
    C  += (long long)blockIdx.z * sC;

    // per-thread cp.async source/dest (2 chunks of 16B => one 32B run per tile)
    const int ldrow = tid >> 1;
    const int ldch  = (tid & 1) * 2;
    const uint32_t ldst = (uint32_t)(ldrow * 80 + ldch * 16);
    const size_t   gofA = (size_t)ldrow * lda + ldch * 8;
    const size_t   gofB = (size_t)ldrow * ldb + ldch * 8;

    // ldmatrix lane addressing (within tile, byte offsets; row stride 80B)
    const int j = lane & 7, g = lane >> 3;
    const uint32_t aOff = (uint32_t)((wm * 64 + (g & 1) * 8 + j) * 80 + (g >> 1) * 16);
    const uint32_t bOff = (uint32_t)((wn * 32 + (g >> 1) * 8 + j) * 80 + (g & 1) * 16);

    float acc[4][4][4];
#pragma unroll
    for (int a = 0; a < 4; a++)
#pragma unroll
        for (int b = 0; b < 4; b++)
#pragma unroll
            for (int r = 0; r < 4; r++) acc[a][b][r] = 0.0f;

    const int NIT = K >> 5;

    auto load_stage = [&](int st, int k0) {
        uint32_t d = sbase + st * STAGEB + ldst;
        const size_t ga = gofA + k0, gb = gofB + k0;
        cp16(d,               Ah + ga); cp16(d + 16,               Ah + ga + 8);
        cp16(d + TB,          Al + ga); cp16(d + TB + 16,          Al + ga + 8);
        cp16(d + 2 * TB,      Bh + gb); cp16(d + 2 * TB + 16,      Bh + gb + 8);
        cp16(d + 3 * TB,      Bl + gb); cp16(d + 3 * TB + 16,      Bl + gb + 8);
    };

    load_stage(0, 0);
    CP_COMMIT();
    if (NIT > 1) load_stage(1, 32);
    CP_COMMIT();

    for (int it = 0; it < NIT; ++it) {
        CP_WAIT(1);
        __syncthreads();
        const uint32_t sb = sbase + (it & 1) * STAGEB;
#pragma unroll
        for (int c = 0; c < 2; ++c) {
            uint32_t bh[8], bl[8];
            ldsm4(bh,     sb + 2 * TB + bOff + c * 32);
            ldsm4(bh + 4, sb + 2 * TB + bOff + 16 * 80 + c * 32);
            ldsm4(bl,     sb + 3 * TB + bOff + c * 32);
            ldsm4(bl + 4, sb + 3 * TB + bOff + 16 * 80 + c * 32);
#pragma unroll
            for (int mi = 0; mi < 4; ++mi) {
                uint32_t ah[4], al[4];
                ldsm4(ah, sb +      aOff + mi * (16 * 80) + c * 32);
                ldsm4(al, sb + TB + aOff + mi * (16 * 80) + c * 32);
#pragma unroll
                for (int ni = 0; ni < 4; ++ni) {
                    mma16816(acc[mi][ni], ah, &bh[ni * 2]);
                    mma16816(acc[mi][ni], ah, &bl[ni * 2]);
                    mma16816(acc[mi][ni], al, &bh[ni * 2]);
                }
            }
        }
        __syncthreads();
        if (it + 2 < NIT) load_stage(it & 1, (it + 2) * 32);
        CP_COMMIT();
    }

    // epilogue
    const int qp = lane & 3, rr = lane >> 2;
#pragma unroll
    for (int mi = 0; mi < 4; ++mi) {
#pragma unroll
        for (int ni = 0; ni < 4; ++ni) {
            const int row = m0 + wm * 64 + mi * 16 + rr;
            const int col = f0 + wn * 32 + ni * 8 + qp * 2;
            float2 v0 = make_float2(acc[mi][ni][0], acc[mi][ni][1]);
            float2 v1 = make_float2(acc[mi][ni][2], acc[mi][ni][3]);
            if (EPI == 0) {
                float2 b = *(const float2*)(bias + col);
                v0.x = tanhf(v0.x + b.x); v0.y = tanhf(v0.y + b.y);
                v1.x = tanhf(v1.x + b.x); v1.y = tanhf(v1.y + b.y);
            } else if (EPI == 1) {
                v0.x *= scale; v0.y *= scale; v1.x *= scale; v1.y *= scale;
            }
            *(float2*)(C + (size_t)row * ldc + col)       = v0;
            *(float2*)(C + (size_t)(row + 8) * ldc + col) = v1;
        }
    }
}

// ===========================================================================
// x (N,D,L) -> flat hi/lo (M,D) bf16 (transpose + split)
// ===========================================================================
__global__ __launch_bounds__(256) void xsplit(const float* __restrict__ x,
                                              bf16* __restrict__ oh, bf16* __restrict__ ol)
{
    __shared__ float t[32][33];
    const int z = blockIdx.z;
    const float* in = x + (size_t)z * DIM * LSEQ;
    const int l0 = blockIdx.x * 32, d0 = blockIdx.y * 32;
    const int xx = threadIdx.x & 31, yy = threadIdx.x >> 5;
#pragma unroll
    for (int i = 0; i < 32; i += 8)
        t[yy + i][xx] = in[(size_t)(d0 + yy + i) * LSEQ + l0 + xx];
    __syncthreads();
#pragma unroll
    for (int i = 0; i < 32; i += 8) {
        float v = t[xx][yy + i];                  // element (d = d0+xx, l = l0+yy+i)
        size_t o = (size_t)(z * LSEQ + l0 + yy + i) * DIM + d0 + xx;
        bf16 h, l; split2(v, h, l);
        oh[o] = h; ol[o] = l;
    }
}

// weights split (elementwise)
__global__ __launch_bounds__(256) void wsplit(const float* __restrict__ w,
                                              bf16* __restrict__ h, bf16* __restrict__ l, int n)
{
    int i = blockIdx.x * 256 + threadIdx.x;
    if (i < n) { bf16 hh, ll; split2(w[i], hh, ll); h[i] = hh; l[i] = ll; }
}

// ===========================================================================
// double instance norm: raw fp32 row -> bf16 hi/lo row
// ===========================================================================
__device__ __forceinline__ float rsum128(float x, volatile float* red, int tid)
{
#pragma unroll
    for (int o = 16; o > 0; o >>= 1) x += __shfl_down_sync(0xffffffffu, x, o);
    if ((tid & 31) == 0) red[tid >> 5] = x;
    __syncthreads();
    float t = (red[0] + red[1]) + (red[2] + red[3]);
    __syncthreads();
    return t;
}

__global__ __launch_bounds__(128) void inorm_split(const float* __restrict__ raw,
                                                   bf16* __restrict__ oh, bf16* __restrict__ ol)
{
    const float4* row = (const float4*)(raw + (size_t)blockIdx.x * FD);
    __shared__ float red[4];
    const int tid = threadIdx.x;
    float4 v = row[tid];

    float s  = rsum128(v.x + v.y + v.z + v.w, red, tid);
    float mu = s * (1.0f / FD);
    v.x -= mu; v.y -= mu; v.z -= mu; v.w -= mu;
    float sq = rsum128(v.x * v.x + v.y * v.y + v.z * v.z + v.w * v.w, red, tid);
    float r1 = rsqrtf(sq * (1.0f / FD) + EPSN);
    v.x *= r1; v.y *= r1; v.z *= r1; v.w *= r1;

    float s2  = rsum128(v.x + v.y + v.z + v.w, red, tid);
    float mu2 = s2 * (1.0f / FD);
    v.x -= mu2; v.y -= mu2; v.z -= mu2; v.w -= mu2;
    float sq2 = rsum128(v.x * v.x + v.y * v.y + v.z * v.z + v.w * v.w, red, tid);
    float r2  = rsqrtf(sq2 * (1.0f / FD) + EPSN);
    v.x *= r2; v.y *= r2; v.z *= r2; v.w *= r2;

    size_t o = (size_t)blockIdx.x * FD + tid * 4;
    bf16 h, l;
    split2(v.x, h, l); oh[o]     = h; ol[o]     = l;
    split2(v.y, h, l); oh[o + 1] = h; ol[o + 1] = l;
    split2(v.z, h, l); oh[o + 2] = h; ol[o + 2] = l;
    split2(v.w, h, l); oh[o + 3] = h; ol[o + 3] = l;
}

// ===========================================================================
// softmax: fp32 scores row -> bf16 hi/lo prob row
// ===========================================================================
__global__ __launch_bounds__(256) void softmax_split(const float* __restrict__ S,
                                                     bf16* __restrict__ ph, bf16* __restrict__ pl)
{
    const float* row = S + (size_t)blockIdx.x * LSEQ;
    __shared__ float red[8];
    const int tid = threadIdx.x;

    float v[9];
    float mx = -1e30f;
#pragma unroll
    for (int i = 0; i < 9; i++) { v[i] = row[tid + i * 256]; mx = fmaxf(mx, v[i]); }
#pragma unroll
    for (int o = 16; o > 0; o >>= 1) mx = fmaxf(mx, __shfl_xor_sync(0xffffffffu, mx, o));
    if ((tid & 31) == 0) red[tid >> 5] = mx;
    __syncthreads();
    mx = red[0];
#pragma unroll
    for (int w = 1; w < 8; w++) mx = fmaxf(mx, red[w]);
    __syncthreads();

    float s = 0.0f;
#pragma unroll
    for (int i = 0; i < 9; i++) { v[i] = expf(v[i] - mx); s += v[i]; }
#pragma unroll
    for (int o = 16; o > 0; o >>= 1) s += __shfl_xor_sync(0xffffffffu, s, o);
    if ((tid & 31) == 0) red[tid >> 5] = s;
    __syncthreads();
    s = ((red[0] + red[1]) + (red[2] + red[3])) + ((red[4] + red[5]) + (red[6] + red[7]));
    float inv = 1.0f / s;

    size_t o0 = (size_t)blockIdx.x * LSEQ + tid;
#pragma unroll
    for (int i = 0; i < 9; i++) {
        float p = v[i] * inv;
        bf16 h, l; split2(p, h, l);
        ph[o0 + i * 256] = h; pl[o0 + i * 256] = l;
    }
}

// ===========================================================================
// V (L,F) -> VT (F,L) per batch, bf16 hi & lo
// ===========================================================================
__global__ __launch_bounds__(256) void vtrans(const bf16* __restrict__ ih, const bf16* __restrict__ il,
                                              bf16* __restrict__ oh, bf16* __restrict__ ol)
{
    __shared__ bf16 t[32][34];
    const int z = blockIdx.z;
    const size_t base = (size_t)z * LSEQ * FD;
    const int f0 = blockIdx.x * 32, l0 = blockIdx.y * 32;
    const int xx = threadIdx.x & 31, yy = threadIdx.x >> 5;

#pragma unroll
    for (int i = 0; i < 32; i += 8)
        t[yy + i][xx] = ih[base + (size_t)(l0 + yy + i) * FD + f0 + xx];
    __syncthreads();
#pragma unroll
    for (int i = 0; i < 32; i += 8)
        oh[base + (size_t)(f0 + yy + i) * LSEQ + l0 + xx] = t[xx][yy + i];
    __syncthreads();
#pragma unroll
    for (int i = 0; i < 32; i += 8)
        t[yy + i][xx] = il[base + (size_t)(l0 + yy + i) * FD + f0 + xx];
    __syncthreads();
#pragma unroll
    for (int i = 0; i < 32; i += 8)
        ol[base + (size_t)(f0 + yy + i) * LSEQ + l0 + xx] = t[xx][yy + i];
}

// ===========================================================================
extern "C" void kernel_launch(void* const* d_in, const int* in_sizes, int n_in,
                              void* d_out, int out_size)
{
    const float* x  = (const float*)d_in[0];
    const float* Wq = (const float*)d_in[1];
    const float* bq = (const float*)d_in[2];
    const float* Wk = (const float*)d_in[3];
    const float* bk = (const float*)d_in[4];
    const float* Wv = (const float*)d_in[5];
    const float* bv = (const float*)d_in[6];
    float* out = (float*)d_out;

    bf16 *pFh, *pFl, *pWh, *pWl, *pQh, *pQl, *pKh, *pKl, *pVh, *pVl, *pVTh, *pVTl, *pPh, *pPl;
    float* pS;
    cudaGetSymbolAddress((void**)&pFh,  g_flat_h);
    cudaGetSymbolAddress((void**)&pFl,  g_flat_l);
    cudaGetSymbolAddress((void**)&pWh,  g_Wh);
    cudaGetSymbolAddress((void**)&pWl,  g_Wl);
    cudaGetSymbolAddress((void**)&pQh,  g_Qh);
    cudaGetSymbolAddress((void**)&pQl,  g_Ql);
    cudaGetSymbolAddress((void**)&pKh,  g_Kh);
    cudaGetSymbolAddress((void**)&pKl,  g_Kl);
    cudaGetSymbolAddress((void**)&pVh,  g_Vh);
    cudaGetSymbolAddress((void**)&pVl,  g_Vl);
    cudaGetSymbolAddress((void**)&pVTh, g_VTh);
    cudaGetSymbolAddress((void**)&pVTl, g_VTl);
    cudaGetSymbolAddress((void**)&pPh,  g_Ph);
    cudaGetSymbolAddress((void**)&pPl,  g_Pl);
    cudaGetSymbolAddress((void**)&pS,   g_S);

    cudaFuncSetAttribute(gemm3<0>, cudaFuncAttributeMaxDynamicSharedMemorySize, GEMM_SMEM);
    cudaFuncSetAttribute(gemm3<1>, cudaFuncAttributeMaxDynamicSharedMemorySize, GEMM_SMEM);
    cudaFuncSetAttribute(gemm3<2>, cudaFuncAttributeMaxDynamicSharedMemorySize, GEMM_SMEM);

    const int WN = FD * DIM;
    // raw QKV staging aliased into g_S (42.5M floats >= 3*9.44M)
    float* qraw = pS;
    float* kraw = pS + MF;
    float* vraw = pS + 2 * MF;

    // 1) transpose+split x, split weights
    xsplit<<<dim3(LSEQ / 32, DIM / 32, NB), 256>>>(x, pFh, pFl);
    wsplit<<<(WN + 255) / 256, 256>>>(Wq, pWh + 0 * WN, pWl + 0 * WN, WN);
    wsplit<<<(WN + 255) / 256, 256>>>(Wk, pWh + 1 * WN, pWl + 1 * WN, WN);
    wsplit<<<(WN + 255) / 256, 256>>>(Wv, pWh + 2 * WN, pWl + 2 * WN, WN);

    // 2) projections -> raw fp32 (tanh applied)
    gemm3<0><<<dim3(FD / 128, MTOT / 128, 1), 256, GEMM_SMEM>>>(
        pFh, pFl, pWh + 0 * WN, pWl + 0 * WN, qraw, bq, DIM, DIM, DIM, FD, 0, 0, 0, 0.f);
    gemm3<0><<<dim3(FD / 128, MTOT / 128, 1), 256, GEMM_SMEM>>>(
        pFh, pFl, pWh + 1 * WN, pWl + 1 * WN, kraw, bk, DIM, DIM, DIM, FD, 0, 0, 0, 0.f);
    gemm3<0><<<dim3(FD / 128, MTOT / 128, 1), 256, GEMM_SMEM>>>(
        pFh, pFl, pWh + 2 * WN, pWl + 2 * WN, vraw, bv, DIM, DIM, DIM, FD, 0, 0, 0, 0.f);

    // 3) double inorm + split
    inorm_split<<<MTOT, 128>>>(qraw, pQh, pQl);
    inorm_split<<<MTOT, 128>>>(kraw, pKh, pKl);
    inorm_split<<<MTOT, 128>>>(vraw, pVh, pVl);

    // 4) V -> VT
    vtrans<<<dim3(FD / 32, LSEQ / 32, NB), 256>>>(pVh, pVl, pVTh, pVTl);

    // 5) scores = (Q K^T) * scale  (overwrites g_S)
    gemm3<1><<<dim3(LSEQ / 128, LSEQ / 128, NB), 256, GEMM_SMEM>>>(
        pQh, pQl, pKh, pKl, pS, nullptr, FD, FD, FD, LSEQ,
        (long long)LSEQ * FD, (long long)LSEQ * FD, (long long)LSEQ * LSEQ, SCORE_SCALE);

    // 6) softmax + split
    softmax_split<<<NB * LSEQ, 256>>>(pS, pPh, pPl);

    // 7) out = P @ V
    gemm3<2><<<dim3(FD / 128, LSEQ / 128, NB), 256, GEMM_SMEM>>>(
        pPh, pPl, pVTh, pVTl, out, nullptr, LSEQ, LSEQ, LSEQ, FD,
        (long long)LSEQ * LSEQ, (long long)FD * LSEQ, (long long)LSEQ * FD, 1.f);
}

// round 4
// speedup vs baseline: 2.9455x; 1.0849x over previous
#include <cuda_runtime.h>
#include <cuda_bf16.h>
#include <cstdint>

#define NB    8
#define DIM   512
#define LSEQ  2304
#define FD    512
#define MTOT  (NB * LSEQ)         // 18432
#define MF    ((size_t)MTOT * FD) // 9437184
#define EPSN  1e-5f
#define SCORE_SCALE 0.044194173824159216f   // 1/sqrt(512)

typedef __nv_bfloat16 bf16;

// ---------------- scratch (device globals) ----------------
__device__ bf16  g_flat_h[MF], g_flat_l[MF];         // x^T hi/lo
__device__ bf16  g_Wh[3][FD * DIM], g_Wl[3][FD * DIM];
__device__ bf16  g_Qh[MF], g_Ql[MF];
__device__ bf16  g_Kh[MF], g_Kl[MF];
__device__ bf16  g_Vh[MF], g_Vl[MF];
__device__ bf16  g_VTh[MF], g_VTl[MF];               // V^T per batch (F, L)
__device__ bf16  g_Ph[(size_t)NB * LSEQ * LSEQ], g_Pl[(size_t)NB * LSEQ * LSEQ];
__device__ float g_S[(size_t)NB * LSEQ * LSEQ];      // scores fp32; front 3*MF floats double as raw QKV

// ---------------- PTX helpers (plain sm_80+ target only) ----------------
__device__ __forceinline__ uint32_t smem_u32(const void* p) {
    uint32_t a;
    asm("{ .reg .u64 t; cvta.to.shared.u64 t, %1; cvt.u32.u64 %0, t; }" : "=r"(a) : "l"(p));
    return a;
}
__device__ __forceinline__ void cp16(uint32_t dst, const void* src) {
    asm volatile("cp.async.cg.shared.global [%0], [%1], 16;" :: "r"(dst), "l"(src));
}
#define CP_COMMIT() asm volatile("cp.async.commit_group;" ::: "memory")
#define CP_WAIT(N)  asm volatile("cp.async.wait_group %0;" :: "n"(N) : "memory")

__device__ __forceinline__ void ldsm4(uint32_t* r, uint32_t addr) {
    asm volatile("ldmatrix.sync.aligned.m8n8.x4.shared.b16 {%0,%1,%2,%3}, [%4];"
                 : "=r"(r[0]), "=r"(r[1]), "=r"(r[2]), "=r"(r[3]) : "r"(addr));
}
__device__ __forceinline__ void mma16816(float* c, const uint32_t* a, const uint32_t* b) {
    asm volatile("mma.sync.aligned.m16n8k16.row.col.f32.bf16.bf16.f32 "
                 "{%0,%1,%2,%3}, {%4,%5,%6,%7}, {%8,%9}, {%0,%1,%2,%3};"
                 : "+f"(c[0]), "+f"(c[1]), "+f"(c[2]), "+f"(c[3])
                 : "r"(a[0]), "r"(a[1]), "r"(a[2]), "r"(a[3]), "r"(b[0]), "r"(b[1]));
}

__device__ __forceinline__ void split2(float v, bf16& h, bf16& l) {
    h = __float2bfloat16_rn(v);
    l = __float2bfloat16_rn(v - __bfloat162float(h));
}

// ---------------- SMEM geometry ----------------
// tile: 128 rows x 32 bf16 (64B data + 16B pad => 80B stride) = 10240 B
#define TB      10240
#define STAGEB  (4 * TB)          // Ah | Al | Bh | Bl
#define GEMM_SMEM (2 * STAGEB)    // 81920 B

// ===========================================================================
// 3xBF16 mma.sync GEMM: C[m,n] = sum_k A[m,k]*B[n,k]   (A,B K-major, split)
// EPI: 0 = tanh(acc+bias), 1 = acc*scale, 2 = none
// ===========================================================================
template <int EPI>
__global__ void __launch_bounds__(256, 2) gemm3(
    const bf16* __restrict__ Ah, const bf16* __restrict__ Al,
    const bf16* __restrict__ Bh, const bf16* __restrict__ Bl,
    float* __restrict__ C, const float* __restrict__ bias,
    int K, int lda, int ldb, int ldc,
    long long sA, long long sB, long long sC, float scale)
{
    extern __shared__ char smem[];
    const uint32_t sbase = smem_u32(smem);
    const int tid  = threadIdx.x;
    const int lane = tid & 31, wid = tid >> 5;
    const int wm = wid >> 2, wn = wid & 3;

    const int m0 = blockIdx.y * 128;
    const int f0 = blockIdx.x * 128;
    Ah += (long long)blockIdx.z * sA + (size_t)m0 * lda;
    Al += (long long)blockIdx.z * sA + (size_t)m0 * lda;
    Bh += (long long)blockIdx.z * sB + (size_t)f0 * ldb;
    Bl += (long long)blockIdx.z * sB + (size_t)f0 * ldb;
    C  += (long long)blockIdx.z * sC;

    const int ldrow = tid >> 1;
    const int ldch  = (tid & 1) * 2;
    const uint32_t ldst = (uint32_t)(ldrow * 80 + ldch * 16);
    const size_t   gofA = (size_t)ldrow * lda + ldch * 8;
    const size_t   gofB = (size_t)ldrow * ldb + ldch * 8;

    const int j = lane & 7, g = lane >> 3;
    const uint32_t aOff = (uint32_t)((wm * 64 + (g & 1) * 8 + j) * 80 + (g >> 1) * 16);
    const uint32_t bOff = (uint32_t)((wn * 32 + (g >> 1) * 8 + j) * 80 + (g & 1) * 16);

    float acc[4][4][4];
#pragma unroll
    for (int a = 0; a < 4; a++)
#pragma unroll
        for (int b = 0; b < 4; b++)
#pragma unroll
            for (int r = 0; r < 4; r++) acc[a][b][r] = 0.0f;

    const int NIT = K >> 5;

    auto load_stage = [&](int st, int k0) {
        uint32_t d = sbase + st * STAGEB + ldst;
        const size_t ga = gofA + k0, gb = gofB + k0;
        cp16(d,               Ah + ga); cp16(d + 16,               Ah + ga + 8);
        cp16(d + TB,          Al + ga); cp16(d + TB + 16,          Al + ga + 8);
        cp16(d + 2 * TB,      Bh + gb); cp16(d + 2 * TB + 16,      Bh + gb + 8);
        cp16(d + 3 * TB,      Bl + gb); cp16(d + 3 * TB + 16,      Bl + gb + 8);
    };

    load_stage(0, 0);
    CP_COMMIT();
    if (NIT > 1) load_stage(1, 32);
    CP_COMMIT();

    for (int it = 0; it < NIT; ++it) {
        CP_WAIT(1);
        __syncthreads();
        const uint32_t sb = sbase + (it & 1) * STAGEB;
#pragma unroll
        for (int c = 0; c < 2; ++c) {
            uint32_t bh[8], bl[8];
            ldsm4(bh,     sb + 2 * TB + bOff + c * 32);
            ldsm4(bh + 4, sb + 2 * TB + bOff + 16 * 80 + c * 32);
            ldsm4(bl,     sb + 3 * TB + bOff + c * 32);
            ldsm4(bl + 4, sb + 3 * TB + bOff + 16 * 80 + c * 32);
#pragma unroll
            for (int mi = 0; mi < 4; ++mi) {
                uint32_t ah[4], al[4];
                ldsm4(ah, sb +      aOff + mi * (16 * 80) + c * 32);
                ldsm4(al, sb + TB + aOff + mi * (16 * 80) + c * 32);
                // Term-outer ordering: same-accumulator MMAs are separated by
                // 3 independent MMAs -> no back-to-back HMMA RAW stalls.
#pragma unroll
                for (int ni = 0; ni < 4; ++ni) mma16816(acc[mi][ni], ah, &bh[ni * 2]);
#pragma unroll
                for (int ni = 0; ni < 4; ++ni) mma16816(acc[mi][ni], ah, &bl[ni * 2]);
#pragma unroll
                for (int ni = 0; ni < 4; ++ni) mma16816(acc[mi][ni], al, &bh[ni * 2]);
            }
        }
        __syncthreads();
        if (it + 2 < NIT) load_stage(it & 1, (it + 2) * 32);
        CP_COMMIT();
    }

    // epilogue
    const int qp = lane & 3, rr = lane >> 2;
#pragma unroll
    for (int mi = 0; mi < 4; ++mi) {
#pragma unroll
        for (int ni = 0; ni < 4; ++ni) {
            const int row = m0 + wm * 64 + mi * 16 + rr;
            const int col = f0 + wn * 32 + ni * 8 + qp * 2;
            float2 v0 = make_float2(acc[mi][ni][0], acc[mi][ni][1]);
            float2 v1 = make_float2(acc[mi][ni][2], acc[mi][ni][3]);
            if (EPI == 0) {
                float2 b = *(const float2*)(bias + col);
                v0.x = tanhf(v0.x + b.x); v0.y = tanhf(v0.y + b.y);
                v1.x = tanhf(v1.x + b.x); v1.y = tanhf(v1.y + b.y);
            } else if (EPI == 1) {
                v0.x *= scale; v0.y *= scale; v1.x *= scale; v1.y *= scale;
            }
            *(float2*)(C + (size_t)row * ldc + col)       = v0;
            *(float2*)(C + (size_t)(row + 8) * ldc + col) = v1;
        }
    }
}

// ===========================================================================
// x (N,D,L) -> flat hi/lo (M,D) bf16 (transpose + split)
// ===========================================================================
__global__ __launch_bounds__(256) void xsplit(const float* __restrict__ x,
                                              bf16* __restrict__ oh, bf16* __restrict__ ol)
{
    __shared__ float t[32][33];
    const int z = blockIdx.z;
    const float* in = x + (size_t)z * DIM * LSEQ;
    const int l0 = blockIdx.x * 32, d0 = blockIdx.y * 32;
    const int xx = threadIdx.x & 31, yy = threadIdx.x >> 5;
#pragma unroll
    for (int i = 0; i < 32; i += 8)
        t[yy + i][xx] = in[(size_t)(d0 + yy + i) * LSEQ + l0 + xx];
    __syncthreads();
#pragma unroll
    for (int i = 0; i < 32; i += 8) {
        float v = t[xx][yy + i];
        size_t o = (size_t)(z * LSEQ + l0 + yy + i) * DIM + d0 + xx;
        bf16 h, l; split2(v, h, l);
        oh[o] = h; ol[o] = l;
    }
}

// weights split: grid.y selects q/k/v
__global__ __launch_bounds__(256) void wsplit(const float* __restrict__ wq,
                                              const float* __restrict__ wk,
                                              const float* __restrict__ wv,
                                              bf16* __restrict__ h, bf16* __restrict__ l)
{
    const int n = FD * DIM;
    const float* w = (blockIdx.y == 0) ? wq : (blockIdx.y == 1) ? wk : wv;
    int i = blockIdx.x * 256 + threadIdx.x;
    if (i < n) {
        bf16 hh, ll; split2(w[i], hh, ll);
        h[blockIdx.y * n + i] = hh; l[blockIdx.y * n + i] = ll;
    }
}

// ===========================================================================
// double instance norm: raw fp32 row -> bf16 hi/lo row (grid.y = q/k/v)
// ===========================================================================
__device__ __forceinline__ float rsum128(float x, volatile float* red, int tid)
{
#pragma unroll
    for (int o = 16; o > 0; o >>= 1) x += __shfl_down_sync(0xffffffffu, x, o);
    if ((tid & 31) == 0) red[tid >> 5] = x;
    __syncthreads();
    float t = (red[0] + red[1]) + (red[2] + red[3]);
    __syncthreads();
    return t;
}

__global__ __launch_bounds__(128) void inorm_split(const float* __restrict__ raw,
                                                   bf16* __restrict__ qh, bf16* __restrict__ ql,
                                                   bf16* __restrict__ kh, bf16* __restrict__ kl,
                                                   bf16* __restrict__ vh, bf16* __restrict__ vl)
{
    const int which = blockIdx.y;
    raw += (size_t)which * MF;
    bf16* oh = (which == 0) ? qh : (which == 1) ? kh : vh;
    bf16* ol = (which == 0) ? ql : (which == 1) ? kl : vl;

    const float4* row = (const float4*)(raw + (size_t)blockIdx.x * FD);
    __shared__ float red[4];
    const int tid = threadIdx.x;
    float4 v = row[tid];

    float s  = rsum128(v.x + v.y + v.z + v.w, red, tid);
    float mu = s * (1.0f / FD);
    v.x -= mu; v.y -= mu; v.z -= mu; v.w -= mu;
    float sq = rsum128(v.x * v.x + v.y * v.y + v.z * v.z + v.w * v.w, red, tid);
    float r1 = rsqrtf(sq * (1.0f / FD) + EPSN);
    v.x *= r1; v.y *= r1; v.z *= r1; v.w *= r1;

    float s2  = rsum128(v.x + v.y + v.z + v.w, red, tid);
    float mu2 = s2 * (1.0f / FD);
    v.x -= mu2; v.y -= mu2; v.z -= mu2; v.w -= mu2;
    float sq2 = rsum128(v.x * v.x + v.y * v.y + v.z * v.z + v.w * v.w, red, tid);
    float r2  = rsqrtf(sq2 * (1.0f / FD) + EPSN);
    v.x *= r2; v.y *= r2; v.z *= r2; v.w *= r2;

    size_t o = (size_t)blockIdx.x * FD + tid * 4;
    bf16 h, l;
    split2(v.x, h, l); oh[o]     = h; ol[o]     = l;
    split2(v.y, h, l); oh[o + 1] = h; ol[o + 1] = l;
    split2(v.z, h, l); oh[o + 2] = h; ol[o + 2] = l;
    split2(v.w, h, l); oh[o + 3] = h; ol[o + 3] = l;
}

// ===========================================================================
// softmax: fp32 scores row -> bf16 hi/lo prob row
// ===========================================================================
__global__ __launch_bounds__(256) void softmax_split(const float* __restrict__ S,
                                                     bf16* __restrict__ ph, bf16* __restrict__ pl)
{
    const float* row = S + (size_t)blockIdx.x * LSEQ;
    __shared__ float red[8];
    const int tid = threadIdx.x;

    float v[9];
    float mx = -1e30f;
#pragma unroll
    for (int i = 0; i < 9; i++) { v[i] = row[tid + i * 256]; mx = fmaxf(mx, v[i]); }
#pragma unroll
    for (int o = 16; o > 0; o >>= 1) mx = fmaxf(mx, __shfl_xor_sync(0xffffffffu, mx, o));
    if ((tid & 31) == 0) red[tid >> 5] = mx;
    __syncthreads();
    mx = red[0];
#pragma unroll
    for (int w = 1; w < 8; w++) mx = fmaxf(mx, red[w]);
    __syncthreads();

    float s = 0.0f;
#pragma unroll
    for (int i = 0; i < 9; i++) { v[i] = expf(v[i] - mx); s += v[i]; }
#pragma unroll
    for (int o = 16; o > 0; o >>= 1) s += __shfl_xor_sync(0xffffffffu, s, o);
    if ((tid & 31) == 0) red[tid >> 5] = s;
    __syncthreads();
    s = ((red[0] + red[1]) + (red[2] + red[3])) + ((red[4] + red[5]) + (red[6] + red[7]));
    float inv = 1.0f / s;

    size_t o0 = (size_t)blockIdx.x * LSEQ + tid;
#pragma unroll
    for (int i = 0; i < 9; i++) {
        float p = v[i] * inv;
        bf16 h, l; split2(p, h, l);
        ph[o0 + i * 256] = h; pl[o0 + i * 256] = l;
    }
}

// ===========================================================================
// V (L,F) -> VT (F,L) per batch, bf16 hi & lo
// ===========================================================================
__global__ __launch_bounds__(256) void vtrans(const bf16* __restrict__ ih, const bf16* __restrict__ il,
                                              bf16* __restrict__ oh, bf16* __restrict__ ol)
{
    __shared__ bf16 t[32][34];
    const int z = blockIdx.z;
    const size_t base = (size_t)z * LSEQ * FD;
    const int f0 = blockIdx.x * 32, l0 = blockIdx.y * 32;
    const int xx = threadIdx.x & 31, yy = threadIdx.x >> 5;

#pragma unroll
    for (int i = 0; i < 32; i += 8)
        t[yy + i][xx] = ih[base + (size_t)(l0 + yy + i) * FD + f0 + xx];
    __syncthreads();
#pragma unroll
    for (int i = 0; i < 32; i += 8)
        oh[base + (size_t)(f0 + yy + i) * LSEQ + l0 + xx] = t[xx][yy + i];
    __syncthreads();
#pragma unroll
    for (int i = 0; i < 32; i += 8)
        t[yy + i][xx] = il[base + (size_t)(l0 + yy + i) * FD + f0 + xx];
    __syncthreads();
#pragma unroll
    for (int i = 0; i < 32; i += 8)
        ol[base + (size_t)(f0 + yy + i) * LSEQ + l0 + xx] = t[xx][yy + i];
}

// ===========================================================================
extern "C" void kernel_launch(void* const* d_in, const int* in_sizes, int n_in,
                              void* d_out, int out_size)
{
    const float* x  = (const float*)d_in[0];
    const float* Wq = (const float*)d_in[1];
    const float* bq = (const float*)d_in[2];
    const float* Wk = (const float*)d_in[3];
    const float* bk = (const float*)d_in[4];
    const float* Wv = (const float*)d_in[5];
    const float* bv = (const float*)d_in[6];
    float* out = (float*)d_out;

    bf16 *pFh, *pFl, *pWh, *pWl, *pQh, *pQl, *pKh, *pKl, *pVh, *pVl, *pVTh, *pVTl, *pPh, *pPl;
    float* pS;
    cudaGetSymbolAddress((void**)&pFh,  g_flat_h);
    cudaGetSymbolAddress((void**)&pFl,  g_flat_l);
    cudaGetSymbolAddress((void**)&pWh,  g_Wh);
    cudaGetSymbolAddress((void**)&pWl,  g_Wl);
    cudaGetSymbolAddress((void**)&pQh,  g_Qh);
    cudaGetSymbolAddress((void**)&pQl,  g_Ql);
    cudaGetSymbolAddress((void**)&pKh,  g_Kh);
    cudaGetSymbolAddress((void**)&pKl,  g_Kl);
    cudaGetSymbolAddress((void**)&pVh,  g_Vh);
    cudaGetSymbolAddress((void**)&pVl,  g_Vl);
    cudaGetSymbolAddress((void**)&pVTh, g_VTh);
    cudaGetSymbolAddress((void**)&pVTl, g_VTl);
    cudaGetSymbolAddress((void**)&pPh,  g_Ph);
    cudaGetSymbolAddress((void**)&pPl,  g_Pl);
    cudaGetSymbolAddress((void**)&pS,   g_S);

    cudaFuncSetAttribute(gemm3<0>, cudaFuncAttributeMaxDynamicSharedMemorySize, GEMM_SMEM);
    cudaFuncSetAttribute(gemm3<1>, cudaFuncAttributeMaxDynamicSharedMemorySize, GEMM_SMEM);
    cudaFuncSetAttribute(gemm3<2>, cudaFuncAttributeMaxDynamicSharedMemorySize, GEMM_SMEM);

    const int WN = FD * DIM;
    float* qraw = pS;            // raw QKV staged in g_S (42.5M floats >= 3*MF)
    float* kraw = pS + MF;
    float* vraw = pS + 2 * MF;

    // 1) transpose+split x, split weights
    xsplit<<<dim3(LSEQ / 32, DIM / 32, NB), 256>>>(x, pFh, pFl);
    wsplit<<<dim3((WN + 255) / 256, 3), 256>>>(Wq, Wk, Wv, pWh, pWl);

    // 2) projections -> raw fp32 (tanh applied)
    gemm3<0><<<dim3(FD / 128, MTOT / 128, 1), 256, GEMM_SMEM>>>(
        pFh, pFl, pWh + 0 * WN, pWl + 0 * WN, qraw, bq, DIM, DIM, DIM, FD, 0, 0, 0, 0.f);
    gemm3<0><<<dim3(FD / 128, MTOT / 128, 1), 256, GEMM_SMEM>>>(
        pFh, pFl, pWh + 1 * WN, pWl + 1 * WN, kraw, bk, DIM, DIM, DIM, FD, 0, 0, 0, 0.f);
    gemm3<0><<<dim3(FD / 128, MTOT / 128, 1), 256, GEMM_SMEM>>>(
        pFh, pFl, pWh + 2 * WN, pWl + 2 * WN, vraw, bv, DIM, DIM, DIM, FD, 0, 0, 0, 0.f);

    // 3) double inorm + split (q/k/v in one launch)
    inorm_split<<<dim3(MTOT, 3), 128>>>(qraw, pQh, pQl, pKh, pKl, pVh, pVl);

    // 4) V -> VT
    vtrans<<<dim3(FD / 32, LSEQ / 32, NB), 256>>>(pVh, pVl, pVTh, pVTl);

    // 5) scores = (Q K^T) * scale  (overwrites g_S)
    gemm3<1><<<dim3(LSEQ / 128, LSEQ / 128, NB), 256, GEMM_SMEM>>>(
        pQh, pQl, pKh, pKl, pS, nullptr, FD, FD, FD, LSEQ,
        (long long)LSEQ * FD, (long long)LSEQ * FD, (long long)LSEQ * LSEQ, SCORE_SCALE);

    // 6) softmax + split
    softmax_split<<<NB * LSEQ, 256>>>(pS, pPh, pPl);

    // 7) out = P @ V
    gemm3<2><<<dim3(FD / 128, LSEQ / 128, NB), 256, GEMM_SMEM>>>(
        pPh, pPl, pVTh, pVTl, out, nullptr, LSEQ, LSEQ, LSEQ, FD,
        (long long)LSEQ * LSEQ, (long long)FD * LSEQ, (long long)LSEQ * FD, 1.f);
}

// round 5
// speedup vs baseline: 3.7290x; 1.2660x over previous
#include <cuda_runtime.h>
#include <cuda_fp16.h>
#include <cstdint>

#define NB    8
#define DIM   512
#define LSEQ  2304
#define FD    512
#define MTOT  (NB * LSEQ)         // 18432
#define MF    ((size_t)MTOT * FD) // 9437184
#define EPSN  1e-5f
#define SCORE_SCALE 0.044194173824159216f   // 1/sqrt(512)

typedef __half fp16;

// ---------------- scratch (device globals) ----------------
__device__ fp16  g_flat_h[MF], g_flat_l[MF];         // x^T hi/lo (A of proj)
__device__ fp16  g_Wh[3][FD * DIM], g_Wl[3][FD * DIM];
__device__ fp16  g_Qh[MF], g_Ql[MF];                 // A of scores: hi+lo
__device__ fp16  g_Kh[MF];                           // B of scores: hi only
__device__ fp16  g_Vh[MF];                           // hi only
__device__ fp16  g_VTh[MF];                          // V^T per batch (F, L), hi only
__device__ fp16  g_Ph[(size_t)NB * LSEQ * LSEQ], g_Pl[(size_t)NB * LSEQ * LSEQ];
__device__ float g_S[(size_t)NB * LSEQ * LSEQ];      // scores fp32; front 3*MF floats = raw QKV

// ---------------- PTX helpers (plain sm_80+ target only) ----------------
__device__ __forceinline__ uint32_t smem_u32(const void* p) {
    uint32_t a;
    asm("{ .reg .u64 t; cvta.to.shared.u64 t, %1; cvt.u32.u64 %0, t; }" : "=r"(a) : "l"(p));
    return a;
}
__device__ __forceinline__ void cp16(uint32_t dst, const void* src) {
    asm volatile("cp.async.cg.shared.global [%0], [%1], 16;" :: "r"(dst), "l"(src));
}
#define CP_COMMIT() asm volatile("cp.async.commit_group;" ::: "memory")
#define CP_WAIT(N)  asm volatile("cp.async.wait_group %0;" :: "n"(N) : "memory")

__device__ __forceinline__ void ldsm4(uint32_t* r, uint32_t addr) {
    asm volatile("ldmatrix.sync.aligned.m8n8.x4.shared.b16 {%0,%1,%2,%3}, [%4];"
                 : "=r"(r[0]), "=r"(r[1]), "=r"(r[2]), "=r"(r[3]) : "r"(addr));
}
__device__ __forceinline__ void mma16816(float* c, const uint32_t* a, const uint32_t* b) {
    asm volatile("mma.sync.aligned.m16n8k16.row.col.f32.f16.f16.f32 "
                 "{%0,%1,%2,%3}, {%4,%5,%6,%7}, {%8,%9}, {%0,%1,%2,%3};"
                 : "+f"(c[0]), "+f"(c[1]), "+f"(c[2]), "+f"(c[3])
                 : "r"(a[0]), "r"(a[1]), "r"(a[2]), "r"(a[3]), "r"(b[0]), "r"(b[1]));
}

__device__ __forceinline__ void split2(float v, fp16& h, fp16& l) {
    h = __float2half_rn(v);
    l = __float2half_rn(v - __half2float(h));
}

// ---------------- SMEM geometry ----------------
// tile: 128 rows x 32 fp16 (64B data + 16B pad => 80B stride) = 10240 B
#define TB 10240

// ===========================================================================
// Split-fp16 mma.sync GEMM: C[m,n] = sum_k A[m,k]*B[n,k]  (A,B K-major)
// NT=3: ah*bh + ah*bl + al*bh  (needs Al, Bl)
// NT=2: ah*bh + al*bh          (A exactly split, B rounded once; no Bl)
// EPI: 0 = tanh(acc+bias), 1 = acc*scale, 2 = none
// ===========================================================================
template <int EPI, int NT>
__global__ void __launch_bounds__(256, 2) gemmN(
    const fp16* __restrict__ Ah, const fp16* __restrict__ Al,
    const fp16* __restrict__ Bh, const fp16* __restrict__ Bl,
    float* __restrict__ C, const float* __restrict__ bias,
    int K, int lda, int ldb, int ldc,
    long long sA, long long sB, long long sC, float scale)
{
    constexpr int NTILES = (NT == 3) ? 4 : 3;     // Ah, Al, Bh [, Bl]
    constexpr int STAGEB = NTILES * TB;

    extern __shared__ char smem[];
    const uint32_t sbase = smem_u32(smem);
    const int tid  = threadIdx.x;
    const int lane = tid & 31, wid = tid >> 5;
    const int wm = wid >> 2, wn = wid & 3;

    const int m0 = blockIdx.y * 128;
    const int f0 = blockIdx.x * 128;
    Ah += (long long)blockIdx.z * sA + (size_t)m0 * lda;
    Al += (long long)blockIdx.z * sA + (size_t)m0 * lda;
    Bh += (long long)blockIdx.z * sB + (size_t)f0 * ldb;
    if (NT == 3) Bl += (long long)blockIdx.z * sB + (size_t)f0 * ldb;
    C  += (long long)blockIdx.z * sC;

    const int ldrow = tid >> 1;
    const int ldch  = (tid & 1) * 2;
    const uint32_t ldst = (uint32_t)(ldrow * 80 + ldch * 16);
    const size_t   gofA = (size_t)ldrow * lda + ldch * 8;
    const size_t   gofB = (size_t)ldrow * ldb + ldch * 8;

    const int j = lane & 7, g = lane >> 3;
    const uint32_t aOff = (uint32_t)((wm * 64 + (g & 1) * 8 + j) * 80 + (g >> 1) * 16);
    const uint32_t bOff = (uint32_t)((wn * 32 + (g >> 1) * 8 + j) * 80 + (g & 1) * 16);

    float acc[4][4][4];
#pragma unroll
    for (int a = 0; a < 4; a++)
#pragma unroll
        for (int b = 0; b < 4; b++)
#pragma unroll
            for (int r = 0; r < 4; r++) acc[a][b][r] = 0.0f;

    const int NIT = K >> 5;

    auto load_stage = [&](int st, int k0) {
        uint32_t d = sbase + st * STAGEB + ldst;
        const size_t ga = gofA + k0, gb = gofB + k0;
        cp16(d,          Ah + ga); cp16(d + 16,          Ah + ga + 8);
        cp16(d + TB,     Al + ga); cp16(d + TB + 16,     Al + ga + 8);
        cp16(d + 2 * TB, Bh + gb); cp16(d + 2 * TB + 16, Bh + gb + 8);
        if (NT == 3) { cp16(d + 3 * TB, Bl + gb); cp16(d + 3 * TB + 16, Bl + gb + 8); }
    };

    load_stage(0, 0);
    CP_COMMIT();
    if (NIT > 1) load_stage(1, 32);
    CP_COMMIT();

    for (int it = 0; it < NIT; ++it) {
        CP_WAIT(1);
        __syncthreads();
        const uint32_t sb = sbase + (it & 1) * STAGEB;
#pragma unroll
        for (int c = 0; c < 2; ++c) {
            uint32_t bh[8], bl[8];
            ldsm4(bh,     sb + 2 * TB + bOff + c * 32);
            ldsm4(bh + 4, sb + 2 * TB + bOff + 16 * 80 + c * 32);
            if (NT == 3) {
                ldsm4(bl,     sb + 3 * TB + bOff + c * 32);
                ldsm4(bl + 4, sb + 3 * TB + bOff + 16 * 80 + c * 32);
            }
#pragma unroll
            for (int mi = 0; mi < 4; ++mi) {
                uint32_t ah[4], al[4];
                ldsm4(ah, sb +      aOff + mi * (16 * 80) + c * 32);
                ldsm4(al, sb + TB + aOff + mi * (16 * 80) + c * 32);
                // term-outer ordering: same-accumulator MMAs separated by 3 indep MMAs
#pragma unroll
                for (int ni = 0; ni < 4; ++ni) mma16816(acc[mi][ni], ah, &bh[ni * 2]);
                if (NT == 3) {
#pragma unroll
                    for (int ni = 0; ni < 4; ++ni) mma16816(acc[mi][ni], ah, &bl[ni * 2]);
                }
#pragma unroll
                for (int ni = 0; ni < 4; ++ni) mma16816(acc[mi][ni], al, &bh[ni * 2]);
            }
        }
        __syncthreads();
        if (it + 2 < NIT) load_stage(it & 1, (it + 2) * 32);
        CP_COMMIT();
    }

    // epilogue
    const int qp = lane & 3, rr = lane >> 2;
#pragma unroll
    for (int mi = 0; mi < 4; ++mi) {
#pragma unroll
        for (int ni = 0; ni < 4; ++ni) {
            const int row = m0 + wm * 64 + mi * 16 + rr;
            const int col = f0 + wn * 32 + ni * 8 + qp * 2;
            float2 v0 = make_float2(acc[mi][ni][0], acc[mi][ni][1]);
            float2 v1 = make_float2(acc[mi][ni][2], acc[mi][ni][3]);
            if (EPI == 0) {
                float2 b = *(const float2*)(bias + col);
                v0.x = tanhf(v0.x + b.x); v0.y = tanhf(v0.y + b.y);
                v1.x = tanhf(v1.x + b.x); v1.y = tanhf(v1.y + b.y);
            } else if (EPI == 1) {
                v0.x *= scale; v0.y *= scale; v1.x *= scale; v1.y *= scale;
            }
            *(float2*)(C + (size_t)row * ldc + col)       = v0;
            *(float2*)(C + (size_t)(row + 8) * ldc + col) = v1;
        }
    }
}

// ===========================================================================
// x (N,D,L) -> flat hi/lo (M,D) fp16 (transpose + split)
// ===========================================================================
__global__ __launch_bounds__(256) void xsplit(const float* __restrict__ x,
                                              fp16* __restrict__ oh, fp16* __restrict__ ol)
{
    __shared__ float t[32][33];
    const int z = blockIdx.z;
    const float* in = x + (size_t)z * DIM * LSEQ;
    const int l0 = blockIdx.x * 32, d0 = blockIdx.y * 32;
    const int xx = threadIdx.x & 31, yy = threadIdx.x >> 5;
#pragma unroll
    for (int i = 0; i < 32; i += 8)
        t[yy + i][xx] = in[(size_t)(d0 + yy + i) * LSEQ + l0 + xx];
    __syncthreads();
#pragma unroll
    for (int i = 0; i < 32; i += 8) {
        float v = t[xx][yy + i];
        size_t o = (size_t)(z * LSEQ + l0 + yy + i) * DIM + d0 + xx;
        fp16 h, l; split2(v, h, l);
        oh[o] = h; ol[o] = l;
    }
}

// weights split: grid.y selects q/k/v
__global__ __launch_bounds__(256) void wsplit(const float* __restrict__ wq,
                                              const float* __restrict__ wk,
                                              const float* __restrict__ wv,
                                              fp16* __restrict__ h, fp16* __restrict__ l)
{
    const int n = FD * DIM;
    const float* w = (blockIdx.y == 0) ? wq : (blockIdx.y == 1) ? wk : wv;
    int i = blockIdx.x * 256 + threadIdx.x;
    if (i < n) {
        fp16 hh, ll; split2(w[i], hh, ll);
        h[blockIdx.y * n + i] = hh; l[blockIdx.y * n + i] = ll;
    }
}

// ===========================================================================
// double instance norm: raw fp32 row -> fp16 (grid.y: 0=Q hi+lo, 1=K hi, 2=V hi)
// ===========================================================================
__device__ __forceinline__ float rsum128(float x, volatile float* red, int tid)
{
#pragma unroll
    for (int o = 16; o > 0; o >>= 1) x += __shfl_down_sync(0xffffffffu, x, o);
    if ((tid & 31) == 0) red[tid >> 5] = x;
    __syncthreads();
    float t = (red[0] + red[1]) + (red[2] + red[3]);
    __syncthreads();
    return t;
}

__global__ __launch_bounds__(128) void inorm_split(const float* __restrict__ raw,
                                                   fp16* __restrict__ qh, fp16* __restrict__ ql,
                                                   fp16* __restrict__ kh, fp16* __restrict__ vh)
{
    const int which = blockIdx.y;
    raw += (size_t)which * MF;
    fp16* oh = (which == 0) ? qh : (which == 1) ? kh : vh;
    fp16* ol = (which == 0) ? ql : nullptr;

    const float4* row = (const float4*)(raw + (size_t)blockIdx.x * FD);
    __shared__ float red[4];
    const int tid = threadIdx.x;
    float4 v = row[tid];

    float s  = rsum128(v.x + v.y + v.z + v.w, red, tid);
    float mu = s * (1.0f / FD);
    v.x -= mu; v.y -= mu; v.z -= mu; v.w -= mu;
    float sq = rsum128(v.x * v.x + v.y * v.y + v.z * v.z + v.w * v.w, red, tid);
    float r1 = rsqrtf(sq * (1.0f / FD) + EPSN);
    v.x *= r1; v.y *= r1; v.z *= r1; v.w *= r1;

    float s2  = rsum128(v.x + v.y + v.z + v.w, red, tid);
    float mu2 = s2 * (1.0f / FD);
    v.x -= mu2; v.y -= mu2; v.z -= mu2; v.w -= mu2;
    float sq2 = rsum128(v.x * v.x + v.y * v.y + v.z * v.z + v.w * v.w, red, tid);
    float r2  = rsqrtf(sq2 * (1.0f / FD) + EPSN);
    v.x *= r2; v.y *= r2; v.z *= r2; v.w *= r2;

    size_t o = (size_t)blockIdx.x * FD + tid * 4;
    fp16 h, l;
    split2(v.x, h, l); oh[o]     = h; if (ol) ol[o]     = l;
    split2(v.y, h, l); oh[o + 1] = h; if (ol) ol[o + 1] = l;
    split2(v.z, h, l); oh[o + 2] = h; if (ol) ol[o + 2] = l;
    split2(v.w, h, l); oh[o + 3] = h; if (ol) ol[o + 3] = l;
}

// ===========================================================================
// softmax: fp32 scores row -> fp16 hi/lo prob row
// ===========================================================================
__global__ __launch_bounds__(256) void softmax_split(const float* __restrict__ S,
                                                     fp16* __restrict__ ph, fp16* __restrict__ pl)
{
    const float* row = S + (size_t)blockIdx.x * LSEQ;
    __shared__ float red[8];
    const int tid = threadIdx.x;

    float v[9];
    float mx = -1e30f;
#pragma unroll
    for (int i = 0; i < 9; i++) { v[i] = row[tid + i * 256]; mx = fmaxf(mx, v[i]); }
#pragma unroll
    for (int o = 16; o > 0; o >>= 1) mx = fmaxf(mx, __shfl_xor_sync(0xffffffffu, mx, o));
    if ((tid & 31) == 0) red[tid >> 5] = mx;
    __syncthreads();
    mx = red[0];
#pragma unroll
    for (int w = 1; w < 8; w++) mx = fmaxf(mx, red[w]);
    __syncthreads();

    float s = 0.0f;
#pragma unroll
    for (int i = 0; i < 9; i++) { v[i] = expf(v[i] - mx); s += v[i]; }
#pragma unroll
    for (int o = 16; o > 0; o >>= 1) s += __shfl_xor_sync(0xffffffffu, s, o);
    if ((tid & 31) == 0) red[tid >> 5] = s;
    __syncthreads();
    s = ((red[0] + red[1]) + (red[2] + red[3])) + ((red[4] + red[5]) + (red[6] + red[7]));
    float inv = 1.0f / s;

    size_t o0 = (size_t)blockIdx.x * LSEQ + tid;
#pragma unroll
    for (int i = 0; i < 9; i++) {
        float p = v[i] * inv;
        fp16 h, l; split2(p, h, l);
        ph[o0 + i * 256] = h; pl[o0 + i * 256] = l;
    }
}

// ===========================================================================
// V (L,F) hi -> VT (F,L) per batch
// ===========================================================================
__global__ __launch_bounds__(256) void vtrans(const fp16* __restrict__ ih,
                                              fp16* __restrict__ oh)
{
    __shared__ fp16 t[32][34];
    const int z = blockIdx.z;
    const size_t base = (size_t)z * LSEQ * FD;
    const int f0 = blockIdx.x * 32, l0 = blockIdx.y * 32;
    const int xx = threadIdx.x & 31, yy = threadIdx.x >> 5;

#pragma unroll
    for (int i = 0; i < 32; i += 8)
        t[yy + i][xx] = ih[base + (size_t)(l0 + yy + i) * FD + f0 + xx];
    __syncthreads();
#pragma unroll
    for (int i = 0; i < 32; i += 8)
        oh[base + (size_t)(f0 + yy + i) * LSEQ + l0 + xx] = t[xx][yy + i];
}

// ===========================================================================
extern "C" void kernel_launch(void* const* d_in, const int* in_sizes, int n_in,
                              void* d_out, int out_size)
{
    const float* x  = (const float*)d_in[0];
    const float* Wq = (const float*)d_in[1];
    const float* bq = (const float*)d_in[2];
    const float* Wk = (const float*)d_in[3];
    const float* bk = (const float*)d_in[4];
    const float* Wv = (const float*)d_in[5];
    const float* bv = (const float*)d_in[6];
    float* out = (float*)d_out;

    fp16 *pFh, *pFl, *pWh, *pWl, *pQh, *pQl, *pKh, *pVh, *pVTh, *pPh, *pPl;
    float* pS;
    cudaGetSymbolAddress((void**)&pFh,  g_flat_h);
    cudaGetSymbolAddress((void**)&pFl,  g_flat_l);
    cudaGetSymbolAddress((void**)&pWh,  g_Wh);
    cudaGetSymbolAddress((void**)&pWl,  g_Wl);
    cudaGetSymbolAddress((void**)&pQh,  g_Qh);
    cudaGetSymbolAddress((void**)&pQl,  g_Ql);
    cudaGetSymbolAddress((void**)&pKh,  g_Kh);
    cudaGetSymbolAddress((void**)&pVh,  g_Vh);
    cudaGetSymbolAddress((void**)&pVTh, g_VTh);
    cudaGetSymbolAddress((void**)&pPh,  g_Ph);
    cudaGetSymbolAddress((void**)&pPl,  g_Pl);
    cudaGetSymbolAddress((void**)&pS,   g_S);

    const int SM3 = 8 * TB;   // NT=3: 2 stages x 4 tiles
    const int SM2 = 6 * TB;   // NT=2: 2 stages x 3 tiles
    cudaFuncSetAttribute((const void*)gemmN<0, 3>, cudaFuncAttributeMaxDynamicSharedMemorySize, SM3);
    cudaFuncSetAttribute((const void*)gemmN<1, 2>, cudaFuncAttributeMaxDynamicSharedMemorySize, SM2);
    cudaFuncSetAttribute((const void*)gemmN<2, 2>, cudaFuncAttributeMaxDynamicSharedMemorySize, SM2);

    const int WN = FD * DIM;
    float* qraw = pS;            // raw QKV staged in g_S (42.5M floats >= 3*MF)
    float* kraw = pS + MF;
    float* vraw = pS + 2 * MF;

    // 1) transpose+split x, split weights
    xsplit<<<dim3(LSEQ / 32, DIM / 32, NB), 256>>>(x, pFh, pFl);
    wsplit<<<dim3((WN + 255) / 256, 3), 256>>>(Wq, Wk, Wv, pWh, pWl);

    // 2) projections -> raw fp32 (tanh applied); 3-term (error ~2^-22)
    gemmN<0, 3><<<dim3(FD / 128, MTOT / 128, 1), 256, SM3>>>(
        pFh, pFl, pWh + 0 * WN, pWl + 0 * WN, qraw, bq, DIM, DIM, DIM, FD, 0, 0, 0, 0.f);
    gemmN<0, 3><<<dim3(FD / 128, MTOT / 128, 1), 256, SM3>>>(
        pFh, pFl, pWh + 1 * WN, pWl + 1 * WN, kraw, bk, DIM, DIM, DIM, FD, 0, 0, 0, 0.f);
    gemmN<0, 3><<<dim3(FD / 128, MTOT / 128, 1), 256, SM3>>>(
        pFh, pFl, pWh + 2 * WN, pWl + 2 * WN, vraw, bv, DIM, DIM, DIM, FD, 0, 0, 0, 0.f);

    // 3) double inorm + split (Q hi+lo; K,V hi only)
    inorm_split<<<dim3(MTOT, 3), 128>>>(qraw, pQh, pQl, pKh, pVh);

    // 4) V -> VT (hi only)
    vtrans<<<dim3(FD / 32, LSEQ / 32, NB), 256>>>(pVh, pVTh);

    // 5) scores = (Q K^T) * scale; 2-term: (qh+ql)*kh
    gemmN<1, 2><<<dim3(LSEQ / 128, LSEQ / 128, NB), 256, SM2>>>(
        pQh, pQl, pKh, nullptr, pS, nullptr, FD, FD, FD, LSEQ,
        (long long)LSEQ * FD, (long long)LSEQ * FD, (long long)LSEQ * LSEQ, SCORE_SCALE);

    // 6) softmax + split
    softmax_split<<<NB * LSEQ, 256>>>(pS, pPh, pPl);

    // 7) out = P @ V; 2-term: (ph+pl)*vh
    gemmN<2, 2><<<dim3(FD / 128, LSEQ / 128, NB), 256, SM2>>>(
        pPh, pPl, pVTh, nullptr, out, nullptr, LSEQ, LSEQ, LSEQ, FD,
        (long long)LSEQ * LSEQ, (long long)FD * LSEQ, (long long)LSEQ * FD, 1.f);
}

// round 6
// speedup vs baseline: 4.0095x; 1.0752x over previous
#include <cuda_runtime.h>
#include <cuda_fp16.h>
#include <cstdint>

#define NB    8
#define DIM   512
#define LSEQ  2304
#define FD    512
#define MTOT  (NB * LSEQ)         // 18432
#define MF    ((size_t)MTOT * FD) // 9437184
#define EPSN  1e-5f
#define SCORE_SCALE 0.044194173824159216f   // 1/sqrt(512)

typedef __half fp16;

// ---------------- scratch (device globals) ----------------
__device__ fp16  g_flat_h[MF], g_flat_l[MF];         // x^T hi/lo (A of proj, 2-term exact side)
__device__ fp16  g_Wh[3][FD * DIM];                  // W rounded once (B side)
__device__ fp16  g_Qh[MF], g_Ql[MF];                 // A of scores: hi+lo
__device__ fp16  g_Kh[MF];                           // B of scores: hi only
__device__ fp16  g_Vh[MF];
__device__ fp16  g_VTh[MF];                          // V^T per batch (F, L)
__device__ fp16  g_Ph[(size_t)NB * LSEQ * LSEQ], g_Pl[(size_t)NB * LSEQ * LSEQ];
__device__ float g_S[(size_t)NB * LSEQ * LSEQ];      // scores fp32; front 3*MF floats = raw QKV

// ---------------- PTX helpers (plain sm_80+ target only) ----------------
__device__ __forceinline__ uint32_t smem_u32(const void* p) {
    uint32_t a;
    asm("{ .reg .u64 t; cvta.to.shared.u64 t, %1; cvt.u32.u64 %0, t; }" : "=r"(a) : "l"(p));
    return a;
}
__device__ __forceinline__ void cp16(uint32_t dst, const void* src) {
    asm volatile("cp.async.cg.shared.global [%0], [%1], 16;" :: "r"(dst), "l"(src));
}
#define CP_COMMIT() asm volatile("cp.async.commit_group;" ::: "memory")
#define CP_WAIT(N)  asm volatile("cp.async.wait_group %0;" :: "n"(N) : "memory")

__device__ __forceinline__ void ldsm4(uint32_t* r, uint32_t addr) {
    asm volatile("ldmatrix.sync.aligned.m8n8.x4.shared.b16 {%0,%1,%2,%3}, [%4];"
                 : "=r"(r[0]), "=r"(r[1]), "=r"(r[2]), "=r"(r[3]) : "r"(addr));
}
__device__ __forceinline__ void mma16816(float* c, const uint32_t* a, const uint32_t* b) {
    asm volatile("mma.sync.aligned.m16n8k16.row.col.f32.f16.f16.f32 "
                 "{%0,%1,%2,%3}, {%4,%5,%6,%7}, {%8,%9}, {%0,%1,%2,%3};"
                 : "+f"(c[0]), "+f"(c[1]), "+f"(c[2]), "+f"(c[3])
                 : "r"(a[0]), "r"(a[1]), "r"(a[2]), "r"(a[3]), "r"(b[0]), "r"(b[1]));
}

__device__ __forceinline__ void split2(float v, fp16& h, fp16& l) {
    h = __float2half_rn(v);
    l = __float2half_rn(v - __half2float(h));
}

// ---------------- SMEM geometry ----------------
// tile: 128 rows x 64 fp16 = 128B/row, XOR-swizzled (no pad) = 16384 B
#define TB      16384
#define STAGEB  (3 * TB)          // Ah | Al | Bh
#define GEMM_SMEM (2 * STAGEB)    // 98304 B (2 CTAs/SM)

// ===========================================================================
// 2-term split-fp16 GEMM: C[m,n] = sum_k (Ah+Al)[m,k] * Bh[n,k]
// K_TILE=64, double buffered, swizzled SMEM.
// EPI: 0 = tanh(acc+bias), 1 = acc*scale, 2 = none
// ===========================================================================
template <int EPI>
__global__ void __launch_bounds__(256, 2) gemm2(
    const fp16* __restrict__ Ah, const fp16* __restrict__ Al,
    const fp16* __restrict__ Bh,
    float* __restrict__ C, const float* __restrict__ bias,
    int K, int lda, int ldb, int ldc,
    long long sA, long long sB, long long sC, float scale)
{
    extern __shared__ char smem[];
    const uint32_t sbase = smem_u32(smem);
    const int tid  = threadIdx.x;
    const int lane = tid & 31, wid = tid >> 5;
    const int wm = wid >> 2, wn = wid & 3;

    const int m0 = blockIdx.y * 128;
    const int f0 = blockIdx.x * 128;
    Ah += (long long)blockIdx.z * sA + (size_t)m0 * lda;
    Al += (long long)blockIdx.z * sA + (size_t)m0 * lda;
    Bh += (long long)blockIdx.z * sB + (size_t)f0 * ldb;
    C  += (long long)blockIdx.z * sC;

    // cp.async mapping: thread t -> row r = t>>1, chunks (t&1)*4 + j (j=0..3)
    const int ldrow  = tid >> 1;
    const int ldcb   = (tid & 1) * 4;
    const int ldxor  = ldrow & 7;
    const size_t gA0 = (size_t)ldrow * lda + ldcb * 8;
    const size_t gB0 = (size_t)ldrow * ldb + ldcb * 8;
    const uint32_t ldRow128 = (uint32_t)(ldrow * 128);

    // ldmatrix mapping
    const int j = lane & 7, g = lane >> 3;
    const int aColSel = g >> 1, bColSel = g & 1;
    const uint32_t aRowB = (uint32_t)((wm * 64 + (g & 1) * 8 + j) * 128);  // + mi*16*128
    const uint32_t bRowB = (uint32_t)((wn * 32 + (g >> 1) * 8 + j) * 128); // + 16*128 for upper
    // xor factor for both A and B lanes is j (row offsets are multiples of 8)

    float acc[4][4][4];
#pragma unroll
    for (int a = 0; a < 4; a++)
#pragma unroll
        for (int b = 0; b < 4; b++)
#pragma unroll
            for (int r = 0; r < 4; r++) acc[a][b][r] = 0.0f;

    const int NIT = K >> 6;   // K / 64

    auto load_stage = [&](int st, int k0) {
        const uint32_t base = sbase + st * STAGEB + ldRow128;
#pragma unroll
        for (int q = 0; q < 4; ++q) {
            const int c16 = ldcb + q;
            const uint32_t d = base + (uint32_t)((c16 ^ ldxor) * 16);
            cp16(d,          Ah + gA0 + k0 + q * 8);
            cp16(d + TB,     Al + gA0 + k0 + q * 8);
            cp16(d + 2 * TB, Bh + gB0 + k0 + q * 8);
        }
    };

    load_stage(0, 0);
    CP_COMMIT();
    if (NIT > 1) load_stage(1, 64);
    CP_COMMIT();

    for (int it = 0; it < NIT; ++it) {
        CP_WAIT(1);
        __syncthreads();
        const uint32_t sb = sbase + (it & 1) * STAGEB;
#pragma unroll
        for (int c = 0; c < 4; ++c) {          // four k16 blocks per stage
            const uint32_t bPhys = (uint32_t)((((2 * c) + bColSel) ^ j) * 16);
            const uint32_t aPhys = (uint32_t)((((2 * c) + aColSel) ^ j) * 16);
            uint32_t bh[8];
            ldsm4(bh,     sb + 2 * TB + bRowB + bPhys);
            ldsm4(bh + 4, sb + 2 * TB + bRowB + 16 * 128 + bPhys);
#pragma unroll
            for (int mi = 0; mi < 4; ++mi) {
                uint32_t ah[4], al[4];
                ldsm4(ah, sb +      aRowB + mi * (16 * 128) + aPhys);
                ldsm4(al, sb + TB + aRowB + mi * (16 * 128) + aPhys);
#pragma unroll
                for (int ni = 0; ni < 4; ++ni) mma16816(acc[mi][ni], ah, &bh[ni * 2]);
#pragma unroll
                for (int ni = 0; ni < 4; ++ni) mma16816(acc[mi][ni], al, &bh[ni * 2]);
            }
        }
        __syncthreads();
        if (it + 2 < NIT) load_stage(it & 1, (it + 2) * 64);
        CP_COMMIT();
    }

    // epilogue
    const int qp = lane & 3, rr = lane >> 2;
#pragma unroll
    for (int mi = 0; mi < 4; ++mi) {
#pragma unroll
        for (int ni = 0; ni < 4; ++ni) {
            const int row = m0 + wm * 64 + mi * 16 + rr;
            const int col = f0 + wn * 32 + ni * 8 + qp * 2;
            float2 v0 = make_float2(acc[mi][ni][0], acc[mi][ni][1]);
            float2 v1 = make_float2(acc[mi][ni][2], acc[mi][ni][3]);
            if (EPI == 0) {
                float2 b = *(const float2*)(bias + col);
                v0.x = tanhf(v0.x + b.x); v0.y = tanhf(v0.y + b.y);
                v1.x = tanhf(v1.x + b.x); v1.y = tanhf(v1.y + b.y);
            } else if (EPI == 1) {
                v0.x *= scale; v0.y *= scale; v1.x *= scale; v1.y *= scale;
            }
            *(float2*)(C + (size_t)row * ldc + col)       = v0;
            *(float2*)(C + (size_t)(row + 8) * ldc + col) = v1;
        }
    }
}

// ===========================================================================
// x (N,D,L) -> flat hi/lo (M,D) fp16 (transpose + split)
// ===========================================================================
__global__ __launch_bounds__(256) void xsplit(const float* __restrict__ x,
                                              fp16* __restrict__ oh, fp16* __restrict__ ol)
{
    __shared__ float t[32][33];
    const int z = blockIdx.z;
    const float* in = x + (size_t)z * DIM * LSEQ;
    const int l0 = blockIdx.x * 32, d0 = blockIdx.y * 32;
    const int xx = threadIdx.x & 31, yy = threadIdx.x >> 5;
#pragma unroll
    for (int i = 0; i < 32; i += 8)
        t[yy + i][xx] = in[(size_t)(d0 + yy + i) * LSEQ + l0 + xx];
    __syncthreads();
#pragma unroll
    for (int i = 0; i < 32; i += 8) {
        float v = t[xx][yy + i];
        size_t o = (size_t)(z * LSEQ + l0 + yy + i) * DIM + d0 + xx;
        fp16 h, l; split2(v, h, l);
        oh[o] = h; ol[o] = l;
    }
}

// weights: round once to fp16 (hi only); grid.y selects q/k/v
__global__ __launch_bounds__(256) void wsplit(const float* __restrict__ wq,
                                              const float* __restrict__ wk,
                                              const float* __restrict__ wv,
                                              fp16* __restrict__ h)
{
    const int n = FD * DIM;
    const float* w = (blockIdx.y == 0) ? wq : (blockIdx.y == 1) ? wk : wv;
    int i = blockIdx.x * 256 + threadIdx.x;
    if (i < n) h[blockIdx.y * n + i] = __float2half_rn(w[i]);
}

// ===========================================================================
// double instance norm: raw fp32 row -> fp16 (grid.y: 0=Q hi+lo, 1=K hi, 2=V hi)
// ===========================================================================
__device__ __forceinline__ float rsum128(float x, volatile float* red, int tid)
{
#pragma unroll
    for (int o = 16; o > 0; o >>= 1) x += __shfl_down_sync(0xffffffffu, x, o);
    if ((tid & 31) == 0) red[tid >> 5] = x;
    __syncthreads();
    float t = (red[0] + red[1]) + (red[2] + red[3]);
    __syncthreads();
    return t;
}

__global__ __launch_bounds__(128) void inorm_split(const float* __restrict__ raw,
                                                   fp16* __restrict__ qh, fp16* __restrict__ ql,
                                                   fp16* __restrict__ kh, fp16* __restrict__ vh)
{
    const int which = blockIdx.y;
    raw += (size_t)which * MF;
    fp16* oh = (which == 0) ? qh : (which == 1) ? kh : vh;
    fp16* ol = (which == 0) ? ql : nullptr;

    const float4* row = (const float4*)(raw + (size_t)blockIdx.x * FD);
    __shared__ float red[4];
    const int tid = threadIdx.x;
    float4 v = row[tid];

    float s  = rsum128(v.x + v.y + v.z + v.w, red, tid);
    float mu = s * (1.0f / FD);
    v.x -= mu; v.y -= mu; v.z -= mu; v.w -= mu;
    float sq = rsum128(v.x * v.x + v.y * v.y + v.z * v.z + v.w * v.w, red, tid);
    float r1 = rsqrtf(sq * (1.0f / FD) + EPSN);
    v.x *= r1; v.y *= r1; v.z *= r1; v.w *= r1;

    float s2  = rsum128(v.x + v.y + v.z + v.w, red, tid);
    float mu2 = s2 * (1.0f / FD);
    v.x -= mu2; v.y -= mu2; v.z -= mu2; v.w -= mu2;
    float sq2 = rsum128(v.x * v.x + v.y * v.y + v.z * v.z + v.w * v.w, red, tid);
    float r2  = rsqrtf(sq2 * (1.0f / FD) + EPSN);
    v.x *= r2; v.y *= r2; v.z *= r2; v.w *= r2;

    size_t o = (size_t)blockIdx.x * FD + tid * 4;
    fp16 h, l;
    split2(v.x, h, l); oh[o]     = h; if (ol) ol[o]     = l;
    split2(v.y, h, l); oh[o + 1] = h; if (ol) ol[o + 1] = l;
    split2(v.z, h, l); oh[o + 2] = h; if (ol) ol[o + 2] = l;
    split2(v.w, h, l); oh[o + 3] = h; if (ol) ol[o + 3] = l;
}

// ===========================================================================
// softmax: fp32 scores row -> fp16 hi/lo prob row
// ===========================================================================
__global__ __launch_bounds__(256) void softmax_split(const float* __restrict__ S,
                                                     fp16* __restrict__ ph, fp16* __restrict__ pl)
{
    const float* row = S + (size_t)blockIdx.x * LSEQ;
    __shared__ float red[8];
    const int tid = threadIdx.x;

    float v[9];
    float mx = -1e30f;
#pragma unroll
    for (int i = 0; i < 9; i++) { v[i] = row[tid + i * 256]; mx = fmaxf(mx, v[i]); }
#pragma unroll
    for (int o = 16; o > 0; o >>= 1) mx = fmaxf(mx, __shfl_xor_sync(0xffffffffu, mx, o));
    if ((tid & 31) == 0) red[tid >> 5] = mx;
    __syncthreads();
    mx = red[0];
#pragma unroll
    for (int w = 1; w < 8; w++) mx = fmaxf(mx, red[w]);
    __syncthreads();

    float s = 0.0f;
#pragma unroll
    for (int i = 0; i < 9; i++) { v[i] = expf(v[i] - mx); s += v[i]; }
#pragma unroll
    for (int o = 16; o > 0; o >>= 1) s += __shfl_xor_sync(0xffffffffu, s, o);
    if ((tid & 31) == 0) red[tid >> 5] = s;
    __syncthreads();
    s = ((red[0] + red[1]) + (red[2] + red[3])) + ((red[4] + red[5]) + (red[6] + red[7]));
    float inv = 1.0f / s;

    size_t o0 = (size_t)blockIdx.x * LSEQ + tid;
#pragma unroll
    for (int i = 0; i < 9; i++) {
        float p = v[i] * inv;
        fp16 h, l; split2(p, h, l);
        ph[o0 + i * 256] = h; pl[o0 + i * 256] = l;
    }
}

// ===========================================================================
// V (L,F) hi -> VT (F,L) per batch
// ===========================================================================
__global__ __launch_bounds__(256) void vtrans(const fp16* __restrict__ ih,
                                              fp16* __restrict__ oh)
{
    __shared__ fp16 t[32][34];
    const int z = blockIdx.z;
    const size_t base = (size_t)z * LSEQ * FD;
    const int f0 = blockIdx.x * 32, l0 = blockIdx.y * 32;
    const int xx = threadIdx.x & 31, yy = threadIdx.x >> 5;

#pragma unroll
    for (int i = 0; i < 32; i += 8)
        t[yy + i][xx] = ih[base + (size_t)(l0 + yy + i) * FD + f0 + xx];
    __syncthreads();
#pragma unroll
    for (int i = 0; i < 32; i += 8)
        oh[base + (size_t)(f0 + yy + i) * LSEQ + l0 + xx] = t[xx][yy + i];
}

// ===========================================================================
extern "C" void kernel_launch(void* const* d_in, const int* in_sizes, int n_in,
                              void* d_out, int out_size)
{
    const float* x  = (const float*)d_in[0];
    const float* Wq = (const float*)d_in[1];
    const float* bq = (const float*)d_in[2];
    const float* Wk = (const float*)d_in[3];
    const float* bk = (const float*)d_in[4];
    const float* Wv = (const float*)d_in[5];
    const float* bv = (const float*)d_in[6];
    float* out = (float*)d_out;

    fp16 *pFh, *pFl, *pWh, *pQh, *pQl, *pKh, *pVh, *pVTh, *pPh, *pPl;
    float* pS;
    cudaGetSymbolAddress((void**)&pFh,  g_flat_h);
    cudaGetSymbolAddress((void**)&pFl,  g_flat_l);
    cudaGetSymbolAddress((void**)&pWh,  g_Wh);
    cudaGetSymbolAddress((void**)&pQh,  g_Qh);
    cudaGetSymbolAddress((void**)&pQl,  g_Ql);
    cudaGetSymbolAddress((void**)&pKh,  g_Kh);
    cudaGetSymbolAddress((void**)&pVh,  g_Vh);
    cudaGetSymbolAddress((void**)&pVTh, g_VTh);
    cudaGetSymbolAddress((void**)&pPh,  g_Ph);
    cudaGetSymbolAddress((void**)&pPl,  g_Pl);
    cudaGetSymbolAddress((void**)&pS,   g_S);

    cudaFuncSetAttribute((const void*)gemm2<0>, cudaFuncAttributeMaxDynamicSharedMemorySize, GEMM_SMEM);
    cudaFuncSetAttribute((const void*)gemm2<1>, cudaFuncAttributeMaxDynamicSharedMemorySize, GEMM_SMEM);
    cudaFuncSetAttribute((const void*)gemm2<2>, cudaFuncAttributeMaxDynamicSharedMemorySize, GEMM_SMEM);

    const int WN = FD * DIM;
    float* qraw = pS;            // raw QKV staged in g_S (42.5M floats >= 3*MF)
    float* kraw = pS + MF;
    float* vraw = pS + 2 * MF;

    // 1) transpose+split x, round weights
    xsplit<<<dim3(LSEQ / 32, DIM / 32, NB), 256>>>(x, pFh, pFl);
    wsplit<<<dim3((WN + 255) / 256, 3), 256>>>(Wq, Wk, Wv, pWh);

    // 2) projections -> raw fp32 (tanh applied); 2-term: (xh+xl)*Wh
    gemm2<0><<<dim3(FD / 128, MTOT / 128, 1), 256, GEMM_SMEM>>>(
        pFh, pFl, pWh + 0 * WN, qraw, bq, DIM, DIM, DIM, FD, 0, 0, 0, 0.f);
    gemm2<0><<<dim3(FD / 128, MTOT / 128, 1), 256, GEMM_SMEM>>>(
        pFh, pFl, pWh + 1 * WN, kraw, bk, DIM, DIM, DIM, FD, 0, 0, 0, 0.f);
    gemm2<0><<<dim3(FD / 128, MTOT / 128, 1), 256, GEMM_SMEM>>>(
        pFh, pFl, pWh + 2 * WN, vraw, bv, DIM, DIM, DIM, FD, 0, 0, 0, 0.f);

    // 3) double inorm + split (Q hi+lo; K,V hi only)
    inorm_split<<<dim3(MTOT, 3), 128>>>(qraw, pQh, pQl, pKh, pVh);

    // 4) V -> VT (hi only)
    vtrans<<<dim3(FD / 32, LSEQ / 32, NB), 256>>>(pVh, pVTh);

    // 5) scores = (Q K^T) * scale; 2-term: (qh+ql)*kh
    gemm2<1><<<dim3(LSEQ / 128, LSEQ / 128, NB), 256, GEMM_SMEM>>>(
        pQh, pQl, pKh, pS, nullptr, FD, FD, FD, LSEQ,
        (long long)LSEQ * FD, (long long)LSEQ * FD, (long long)LSEQ * LSEQ, SCORE_SCALE);

    // 6) softmax + split
    softmax_split<<<NB * LSEQ, 256>>>(pS, pPh, pPl);

    // 7) out = P @ V; 2-term: (ph+pl)*vh
    gemm2<2><<<dim3(FD / 128, LSEQ / 128, NB), 256, GEMM_SMEM>>>(
        pPh, pPl, pVTh, out, nullptr, LSEQ, LSEQ, LSEQ, FD,
        (long long)LSEQ * LSEQ, (long long)FD * LSEQ, (long long)LSEQ * FD, 1.f);
}